// round 13
// baseline (speedup 1.0000x reference)
#include <cuda_runtime.h>
#include <cstdint>

#define CIN  8
#define COUT 8
#define HH   1024
#define WW   1024
#define KK   31

#define NT   256                 // 8 warps
#define RY   8                   // output rows per CTA
#define TXC  256                 // output cols per CTA (8 warps x 32 px)
#define NROWS (RY + 30)          // 38 staged input rows
#define WPC   146                // packed words per parity copy
#define ROWB  (2 * WPC * 4)      // 1168 bytes per row (copy0[146], copy1[146])

#define OFF_SA 0
#define SA_BYTES (NROWS * ROWB)              // 44384
#define OFF_W   ((SA_BYTES + 127) & ~127)    // 44416
#define W_BYTES (31 * 2 * 32 * 8)            // 15872
#define SMEM_TOTAL (OFF_W + W_BYTES)         // 60288

static __device__ __forceinline__ uint32_t smem_u32(const void* p) {
    uint32_t a;
    asm("{ .reg .u64 t; cvta.to.shared.u64 t, %1; cvt.u32.u64 %0, t; }" : "=r"(a) : "l"(p));
    return a;
}
// pack two fp32 -> (f16lo, f16hi) in one b32
static __device__ __forceinline__ uint32_t packh(float lo, float hi) {
    uint32_t r;
    asm("{ .reg .f16 l, h; cvt.rn.f16.f32 l, %1; cvt.rn.f16.f32 h, %2; mov.b32 %0, {l, h}; }"
        : "=r"(r) : "f"(lo), "f"(hi));
    return r;
}
static __device__ __forceinline__ uint32_t lds32(uint32_t a) {
    uint32_t v;
    asm volatile("ld.shared.b32 %0, [%1];" : "=r"(v) : "r"(a));
    return v;
}
static __device__ __forceinline__ uint2 lds64(uint32_t a) {
    uint2 v;
    asm volatile("ld.shared.v2.b32 {%0,%1}, [%2];" : "=r"(v.x), "=r"(v.y) : "r"(a));
    return v;
}
// D(16px x 8co) += A(16px x 16k) * B(16k x 8co), fp16 in, fp32 acc
static __device__ __forceinline__ void mma16(float* c,
                                             uint32_t a0, uint32_t a1,
                                             uint32_t a2, uint32_t a3,
                                             uint2 b) {
    asm volatile("mma.sync.aligned.m16n8k16.row.col.f32.f16.f16.f32 "
                 "{%0,%1,%2,%3}, {%4,%5,%6,%7}, {%8,%9}, {%0,%1,%2,%3};"
                 : "+f"(c[0]), "+f"(c[1]), "+f"(c[2]), "+f"(c[3])
                 : "r"(a0), "r"(a1), "r"(a2), "r"(a3), "r"(b.x), "r"(b.y));
}

__global__ __launch_bounds__(NT, 2)
void conv_mma_kernel(const float* __restrict__ sig,
                     const float* __restrict__ wgt,
                     const float* __restrict__ bias,
                     float* __restrict__ out)
{
    extern __shared__ char smem[];
    const uint32_t sb = smem_u32(smem);
    const int tid  = threadIdx.x;
    const int wid  = tid >> 5;
    const int lane = tid & 31;
    const int X0 = blockIdx.x * TXC;
    const int Y0 = blockIdx.y * RY;
    const int ci = blockIdx.z;

    // ---- stage input rows as fp16, two parity-shifted packed copies ----
    const float* sigc = sig + (size_t)ci * (HH * WW);
    for (int idx = tid; idx < NROWS * 2 * WPC; idx += NT) {
        const int rr  = idx / (2 * WPC);
        const int rem = idx - rr * (2 * WPC);
        const int cp  = rem / WPC;
        const int w   = rem - cp * WPC;
        const int gr  = Y0 - 15 + rr;
        const int lc0 = 2 * w + cp;
        float v0 = 0.0f, v1 = 0.0f;
        if ((unsigned)gr < (unsigned)HH) {
            const float* srow = sigc + (size_t)gr * WW;
            const int g0 = X0 - 16 + lc0;
            const int g1 = g0 + 1;
            if ((unsigned)g0 < (unsigned)WW) v0 = srow[g0];
            if ((unsigned)g1 < (unsigned)WW) v1 = srow[g1];
        }
        ((uint32_t*)(smem + OFF_SA))[rr * (2 * WPC) + cp * WPC + w] = packh(v0, v1);
    }

    // ---- stage B fragments per lane: n = lane>>2, k0 = lane&3 ----
    uint2* wf = (uint2*)(smem + OFF_W);
    for (int idx = tid; idx < 31 * 2 * 32; idx += NT) {
        const int i  = idx >> 6;
        const int t  = (idx >> 5) & 1;
        const int ln = idx & 31;
        const int n  = ln >> 2;
        const int k0 = ln & 3;
        const int j  = 16 * t + 2 * k0;
        const float* wp = wgt + ((size_t)(n * CIN + ci) * KK + i) * KK;
        const float w0 = wp[j];
        const float w1 = wp[j + 1];
        const float w2 = wp[j + 8];
        const float w3 = (j + 9 < KK) ? wp[j + 9] : 0.0f;   // tap 31 padded
        wf[idx] = make_uint2(packh(w0, w1), packh(w2, w3));
    }
    __syncthreads();

    // ---- compute ----
    const int m0  = lane >> 2;
    const int k0l = lane & 3;
    const int par = (m0 + 1) & 1;

    float acc[2][RY][4];
#pragma unroll
    for (int s = 0; s < 2; ++s)
#pragma unroll
        for (int y = 0; y < RY; ++y)
#pragma unroll
            for (int q = 0; q < 4; ++q)
                acc[s][y][q] = 0.0f;

    // A base for strip 0, chunk t: lq = wid*32 + 16t + 1 + m0 + 2*k0l
    // strip 1 = strip 0 + 32B; within-strip regs at +0,+16,+32; boundary shared.
    uint32_t aoff[2];
#pragma unroll
    for (int t = 0; t < 2; ++t) {
        const int lq = wid * 32 + 16 * t + 1 + m0 + 2 * k0l;
        aoff[t] = (uint32_t)(par * (WPC * 4) + (((lq - par) >> 1) << 2));
    }
    const uint32_t sa_base = sb + OFF_SA;
    const uint32_t b_base  = sb + OFF_W + (uint32_t)lane * 8u;

    const int rlo = (Y0 - 15 > 0) ? Y0 - 15 : 0;
    const int rhi = (Y0 + RY + 14 < HH - 1) ? Y0 + RY + 14 : HH - 1;
    // interior: id0 = r - Y0 + 15 in [7, 30] -> all 8 y8 valid
    const int ilo = (rlo > Y0 - 8)  ? rlo : Y0 - 8;
    const int ihi = (rhi < Y0 + 15) ? rhi : Y0 + 15;

    // ---- leading edge rows (guarded) ----
#pragma unroll 1
    for (int r = rlo; r < ilo; ++r) {
        const int rr  = r - (Y0 - 15);
        const int id0 = r - Y0 + 15;
        const uint32_t arow = sa_base + (uint32_t)rr * ROWB;
#pragma unroll
        for (int t = 0; t < 2; ++t) {
            const uint32_t p0 = arow + aoff[t];
            const uint32_t a0 = lds32(p0),      aM = lds32(p0 + 16);
            const uint32_t aX = lds32(p0 + 32), aN = lds32(p0 + 48);
            const uint32_t aZ = lds32(p0 + 64);
#pragma unroll
            for (int y8 = 0; y8 < RY; ++y8) {
                const int i = id0 - y8;
                if ((unsigned)i <= 30u) {
                    const uint2 b = lds64(b_base + (uint32_t)((i * 2 + t) * 256));
                    mma16(acc[0][y8], a0, aM, aM, aX, b);
                    mma16(acc[1][y8], aX, aN, aN, aZ, b);
                }
            }
        }
    }

    // ---- interior rows (branch-free, B prefetched) ----
#pragma unroll 1
    for (int r = ilo; r <= ihi; ++r) {
        const int rr  = r - (Y0 - 15);
        const int id0 = r - Y0 + 15;
        const uint32_t arow = sa_base + (uint32_t)rr * ROWB;
#pragma unroll
        for (int t = 0; t < 2; ++t) {
            const uint32_t p0 = arow + aoff[t];
            const uint32_t a0 = lds32(p0),      aM = lds32(p0 + 16);
            const uint32_t aX = lds32(p0 + 32), aN = lds32(p0 + 48);
            const uint32_t aZ = lds32(p0 + 64);

            uint2 b[RY];
#pragma unroll
            for (int y8 = 0; y8 < RY; ++y8)
                b[y8] = lds64(b_base + (uint32_t)(((id0 - y8) * 2 + t) * 256));

#pragma unroll
            for (int y8 = 0; y8 < RY; ++y8) {
                mma16(acc[0][y8], a0, aM, aM, aX, b[y8]);
                mma16(acc[1][y8], aX, aN, aN, aZ, b[y8]);
            }
        }
    }

    // ---- trailing edge rows (guarded) ----
#pragma unroll 1
    for (int r = ihi + 1; r <= rhi; ++r) {
        const int rr  = r - (Y0 - 15);
        const int id0 = r - Y0 + 15;
        const uint32_t arow = sa_base + (uint32_t)rr * ROWB;
#pragma unroll
        for (int t = 0; t < 2; ++t) {
            const uint32_t p0 = arow + aoff[t];
            const uint32_t a0 = lds32(p0),      aM = lds32(p0 + 16);
            const uint32_t aX = lds32(p0 + 32), aN = lds32(p0 + 48);
            const uint32_t aZ = lds32(p0 + 64);
#pragma unroll
            for (int y8 = 0; y8 < RY; ++y8) {
                const int i = id0 - y8;
                if ((unsigned)i <= 30u) {
                    const uint2 b = lds64(b_base + (uint32_t)((i * 2 + t) * 256));
                    mma16(acc[0][y8], a0, aM, aM, aX, b);
                    mma16(acc[1][y8], aX, aN, aN, aZ, b);
                }
            }
        }
    }

    // ---- epilogue: D c0:(m0,2k0) c1:(m0,2k0+1) c2:(m0+8,2k0) c3:(m0+8,2k0+1) ----
    const float bv  = bias[ci];
    const int co0   = 2 * k0l;
    const size_t plane = (size_t)CIN * HH * WW;

#pragma unroll
    for (int s = 0; s < 2; ++s) {
        const int px = X0 + wid * 32 + s * 16 + m0;
#pragma unroll
        for (int y8 = 0; y8 < RY; ++y8) {
            const int y = Y0 + y8;
            float* b0p = out + (((size_t)co0 * CIN + ci) * HH + y) * WW + px;
            float* b1p = b0p + plane;
            b0p[0] = acc[s][y8][0] + bv;
            b1p[0] = acc[s][y8][1] + bv;
            b0p[8] = acc[s][y8][2] + bv;
            b1p[8] = acc[s][y8][3] + bv;
        }
    }
}

extern "C" void kernel_launch(void* const* d_in, const int* in_sizes, int n_in,
                              void* d_out, int out_size)
{
    const float* sig  = (const float*)d_in[0];   // [1, 8, 1024, 1024]
    const float* wgt  = (const float*)d_in[1];   // [8, 8, 31, 31]
    const float* bias = (const float*)d_in[2];   // [8]
    float* out = (float*)d_out;                  // [8, 8, 1024, 1024]

    cudaFuncSetAttribute(conv_mma_kernel,
                         cudaFuncAttributeMaxDynamicSharedMemorySize, SMEM_TOTAL);
    dim3 grid(WW / TXC, HH / RY, CIN);           // (4, 128, 8) = 4096 blocks
    conv_mma_kernel<<<grid, NT, SMEM_TOTAL>>>(sig, wgt, bias, out);
}